// round 6
// baseline (speedup 1.0000x reference)
#include <cuda_runtime.h>

#define W 512
#define H 512
#define PLANES 48
#define TX 128         // output tile width
#define TY 16          // output tile height
#define HALO 5
#define NCOL 138       // TX + 2*HALO intermediate columns
#define PSTRIDE 140    // u64 stride   (1120 B, 16B-aligned rows)
#define CSTRIDE 140    // float stride (560 B, 16B-aligned rows)
#define NTH 288

typedef unsigned long long u64;

__device__ double g_accum;
__device__ unsigned int g_count;

// Gaussian taps exp(-d^2/4.5), normalized in double at compile time.
#define E0d 1.0
#define E1d 0.8007374029168081
#define E2d 0.4111122905071874
#define E3d 0.1353352832366127
#define E4d 0.0285655007845531
#define E5d 0.0038659201394728
#define ESd (E0d + 2.0*(E1d+E2d+E3d+E4d+E5d))
#define GW0 ((float)(E5d/ESd))
#define GW1 ((float)(E4d/ESd))
#define GW2 ((float)(E3d/ESd))
#define GW3 ((float)(E2d/ESd))
#define GW4 ((float)(E1d/ESd))
#define GW5 ((float)(E0d/ESd))

__device__ __forceinline__ u64 pack2(float a, float b) {
    u64 r; asm("mov.b64 %0, {%1, %2};" : "=l"(r) : "f"(a), "f"(b)); return r;
}
__device__ __forceinline__ void unpack2(u64 v, float& a, float& b) {
    asm("mov.b64 {%0, %1}, %2;" : "=f"(a), "=f"(b) : "l"(v));
}
__device__ __forceinline__ u64 fma2(u64 a, u64 b, u64 c) {
    u64 d; asm("fma.rn.f32x2 %0, %1, %2, %3;" : "=l"(d) : "l"(a), "l"(b), "l"(c)); return d;
}
__device__ __forceinline__ u64 mul2(u64 a, u64 b) {
    u64 d; asm("mul.rn.f32x2 %0, %1, %2;" : "=l"(d) : "l"(a), "l"(b)); return d;
}

// Vertical pass: one column strip per thread, 8 output rows from 18 input
// rows, all in registers. Packed (x,y) and (x2,y2) chains + scalar xy.
template<bool GUARD>
__device__ __forceinline__ void phaseA(const float* __restrict__ p1,
                                       const float* __restrict__ p2,
                                       int row0, int col0, int tid,
                                       u64 (*vhV)[PSTRIDE], u64 (*vhS)[PSTRIDE],
                                       float (*vhC)[CSTRIDE],
                                       const float* gw, const u64* gw2) {
    const int gi = tid / NCOL;          // row group 0..1
    const int cc = tid - gi * NCOL;     // column 0..137
    const int gc = col0 + cc - HALO;
    const int rbase = row0 + gi * 8 - HALO;
    const bool colOk = !GUARD || ((unsigned)gc < (unsigned)W);

    u64 aV[8], aS[8];
    float aC[8];
#pragma unroll
    for (int i = 0; i < 8; i++) { aV[i] = 0ull; aS[i] = 0ull; aC[i] = 0.f; }

#pragma unroll
    for (int j = 0; j < 18; j++) {
        const int gr = rbase + j;
        float x = 0.f, y = 0.f;
        if (!GUARD || (colOk && (unsigned)gr < (unsigned)H)) {
            const int off = gr * W + gc;
            x = p1[off];
            y = p2[off];
        }
        const u64 v  = pack2(x, y);
        const u64 sq = mul2(v, v);
        const float cr = x * y;
#pragma unroll
        for (int i = 0; i < 8; i++) {
            const int k = j - i;        // compile-time tap index
            if (k >= 0 && k < 11) {
                const int ks = (k < 10 - k) ? k : (10 - k);  // symmetric tap
                aV[i] = fma2(gw2[ks], v,  aV[i]);
                aS[i] = fma2(gw2[ks], sq, aS[i]);
                aC[i] += gw[ks] * cr;
            }
        }
    }
    const int r0 = gi * 8;
#pragma unroll
    for (int i = 0; i < 8; i++) {
        vhV[r0 + i][cc] = aV[i];
        vhS[r0 + i][cc] = aS[i];
        vhC[r0 + i][cc] = aC[i];
    }
}

__launch_bounds__(NTH, 3)
__global__ void ssim_fused(const float* __restrict__ img1,
                           const float* __restrict__ img2,
                           float* __restrict__ out) {
    __shared__ __align__(16) u64   vhV[TY][PSTRIDE];   // (hx, hy)    17920 B
    __shared__ __align__(16) u64   vhS[TY][PSTRIDE];   // (hxx, hyy)  17920 B
    __shared__ __align__(16) float vhC[TY][CSTRIDE];   // hxy          8960 B
    __shared__ float wpart[NTH / 32];

    // only 6 distinct taps kept live (symmetry)
    const float gw[6] = {GW0, GW1, GW2, GW3, GW4, GW5};
    u64 gw2[6];
#pragma unroll
    for (int k = 0; k < 6; k++) gw2[k] = pack2(gw[k], gw[k]);

    const int tid   = threadIdx.x;
    const int plane = blockIdx.z;
    const int row0  = blockIdx.y * TY;
    const int col0  = blockIdx.x * TX;
    const float* p1 = img1 + (size_t)plane * (W * H);
    const float* p2 = img2 + (size_t)plane * (W * H);

    // ---------------- Phase A: vertical pass --------------------------------
    if (tid < 2 * NCOL) {
        const bool interior = (row0 >= HALO) && (row0 + TY + HALO <= H) &&
                              (col0 >= HALO) && (col0 + TX + HALO <= W);
        if (interior)
            phaseA<false>(p1, p2, row0, col0, tid, vhV, vhS, vhC, gw, gw2);
        else
            phaseA<true >(p1, p2, row0, col0, tid, vhV, vhS, vhC, gw, gw2);
    }
    __syncthreads();

    // ---------------- Phase B: horizontal pass + SSIM -----------------------
    // 256 threads: r = tid>>4 (16 rows), g = tid&15 (16 col groups of 8).
    // Sequential quantity passes keep register pressure under the 64-reg cap
    // so every vh element is loaded from smem exactly once.
    float local = 0.f;
    if (tid < 256) {
        const int r  = tid >> 4;
        const int c0 = (tid & 15) * 8;

        const float C1 = 1e-4f;
        const float C2 = 9e-4f;

        // -- pass 1: V = (mu1, mu2) packed --
        u64 mV[8];
        {
            u64 fV[18];
            const ulonglong2* rp = reinterpret_cast<const ulonglong2*>(&vhV[r][c0]);
#pragma unroll
            for (int v = 0; v < 9; v++) { ulonglong2 t = rp[v]; fV[2*v] = t.x; fV[2*v+1] = t.y; }
#pragma unroll
            for (int i = 0; i < 8; i++) {
                u64 acc = 0ull;
#pragma unroll
                for (int k = 0; k < 11; k++) {
                    const int ks = (k < 10 - k) ? k : (10 - k);
                    acc = fma2(gw2[ks], fV[i + k], acc);
                }
                mV[i] = acc;
            }
        }

        // -- pass 2: S = (vxx, vyy); fold with mV into 3 scalars per output --
        float mu12[8], musq[8], ssum[8];
        {
            u64 fS[18];
            const ulonglong2* rp = reinterpret_cast<const ulonglong2*>(&vhS[r][c0]);
#pragma unroll
            for (int v = 0; v < 9; v++) { ulonglong2 t = rp[v]; fS[2*v] = t.x; fS[2*v+1] = t.y; }
#pragma unroll
            for (int i = 0; i < 8; i++) {
                u64 acc = 0ull;
#pragma unroll
                for (int k = 0; k < 11; k++) {
                    const int ks = (k < 10 - k) ? k : (10 - k);
                    acc = fma2(gw2[ks], fS[i + k], acc);
                }
                float mu1, mu2, vxx, vyy;
                unpack2(mV[i], mu1, mu2);
                unpack2(acc,   vxx, vyy);
                const float ms = mu1 * mu1 + mu2 * mu2;
                mu12[i] = mu1 * mu2;
                musq[i] = ms;
                ssum[i] = (vxx + vyy) - ms;     // s1 + s2
            }
        }

        // -- pass 3: C = vxy; finish SSIM --
        {
            float fC[20];
            const float4* rp = reinterpret_cast<const float4*>(&vhC[r][c0]);
#pragma unroll
            for (int v = 0; v < 5; v++) {
                float4 t = rp[v];
                fC[4*v+0] = t.x; fC[4*v+1] = t.y; fC[4*v+2] = t.z; fC[4*v+3] = t.w;
            }
#pragma unroll
            for (int i = 0; i < 8; i++) {
                float mC = 0.f;
#pragma unroll
                for (int k = 0; k < 11; k++) {
                    const int ks = (k < 10 - k) ? k : (10 - k);
                    mC += gw[ks] * fC[i + k];
                }
                const float s12 = mC - mu12[i];
                const float num = (2.f * mu12[i] + C1) * (2.f * s12 + C2);
                const float den = (musq[i] + C1) * (ssum[i] + C2 + 1e-6f);
                local += __fdividef(num, den);
            }
        }
    }

    // ---------------- Reduction ----------------------------------------------
#pragma unroll
    for (int off = 16; off > 0; off >>= 1)
        local += __shfl_down_sync(0xffffffffu, local, off);
    if ((tid & 31) == 0) wpart[tid >> 5] = local;
    __syncthreads();
    if (tid == 0) {
        float bs = 0.f;
#pragma unroll
        for (int wv = 0; wv < NTH / 32; wv++) bs += wpart[wv];
        atomicAdd(&g_accum, (double)bs);
        __threadfence();
        const unsigned total = gridDim.x * gridDim.y * gridDim.z;
        if (atomicAdd(&g_count, 1u) == total - 1) {
            const double acc = atomicAdd(&g_accum, 0.0);
            out[0] = (float)(acc / ((double)PLANES * (double)W * (double)H));
            g_accum = 0.0;   // reset so every graph replay is identical
            g_count = 0u;
        }
    }
}

extern "C" void kernel_launch(void* const* d_in, const int* in_sizes, int n_in,
                              void* d_out, int out_size) {
    const float* img1 = (const float*)d_in[0];
    const float* img2 = (const float*)d_in[1];
    float* out = (float*)d_out;

    dim3 grid(W / TX, H / TY, PLANES);
    ssim_fused<<<grid, NTH>>>(img1, img2, out);
}

// round 7
// speedup vs baseline: 1.2156x; 1.2156x over previous
#include <cuda_runtime.h>

#define W 512
#define H 512
#define PLANES 48
#define TX 64          // output tile width
#define TY 32          // output tile height
#define HALO 5
#define NCOL 74        // TX + 2*HALO columns of intermediates
#define PSTRIDE 74     // u64 stride (148 words ≡ 20 mod 32 -> conflict-light 16B loads)
#define CSTRIDE 76     // float stride (76 ≡ 12 mod 32)
#define NTH 320

typedef unsigned long long u64;

__device__ double g_accum;
__device__ unsigned int g_count;

// Gaussian taps exp(-d^2/4.5), normalized in double at compile time.
#define E0d 1.0
#define E1d 0.8007374029168081
#define E2d 0.4111122905071874
#define E3d 0.1353352832366127
#define E4d 0.0285655007845531
#define E5d 0.0038659201394728
#define ESd (E0d + 2.0*(E1d+E2d+E3d+E4d+E5d))
#define GW0 ((float)(E5d/ESd))
#define GW1 ((float)(E4d/ESd))
#define GW2 ((float)(E3d/ESd))
#define GW3 ((float)(E2d/ESd))
#define GW4 ((float)(E1d/ESd))
#define GW5 ((float)(E0d/ESd))

__device__ __forceinline__ u64 pack2(float a, float b) {
    u64 r; asm("mov.b64 %0, {%1, %2};" : "=l"(r) : "f"(a), "f"(b)); return r;
}
__device__ __forceinline__ void unpack2(u64 v, float& a, float& b) {
    asm("mov.b64 {%0, %1}, %2;" : "=f"(a), "=f"(b) : "l"(v));
}
__device__ __forceinline__ u64 fma2(u64 a, u64 b, u64 c) {
    u64 d; asm("fma.rn.f32x2 %0, %1, %2, %3;" : "=l"(d) : "l"(a), "l"(b), "l"(c)); return d;
}
__device__ __forceinline__ u64 mul2(u64 a, u64 b) {
    u64 d; asm("mul.rn.f32x2 %0, %1, %2;" : "=l"(d) : "l"(a), "l"(b)); return d;
}

// Vertical pass: one column strip per thread, 8 output rows from 18 input
// rows, all in registers. Packed (x,y) and (x2,y2) chains + scalar xy.
template<bool GUARD>
__device__ __forceinline__ void phaseA(const float* __restrict__ p1,
                                       const float* __restrict__ p2,
                                       int row0, int col0, int tid,
                                       u64 (*vhV)[PSTRIDE], u64 (*vhS)[PSTRIDE],
                                       float (*vhC)[CSTRIDE],
                                       const float* gw, const u64* gw2) {
    const int gi = tid / NCOL;          // row group 0..3
    const int cc = tid - gi * NCOL;     // column 0..73
    const int gc = col0 + cc - HALO;
    const int rbase = row0 + gi * 8 - HALO;
    const bool colOk = !GUARD || ((unsigned)gc < (unsigned)W);

    u64 aV[8], aS[8];
    float aC[8];
#pragma unroll
    for (int i = 0; i < 8; i++) { aV[i] = 0ull; aS[i] = 0ull; aC[i] = 0.f; }

#pragma unroll
    for (int j = 0; j < 18; j++) {
        const int gr = rbase + j;
        float x = 0.f, y = 0.f;
        if (!GUARD || (colOk && (unsigned)gr < (unsigned)H)) {
            const int off = gr * W + gc;
            x = p1[off];
            y = p2[off];
        }
        const u64 v  = pack2(x, y);
        const u64 sq = mul2(v, v);
        const float cr = x * y;
#pragma unroll
        for (int i = 0; i < 8; i++) {
            const int k = j - i;        // compile-time tap index
            if (k >= 0 && k < 11) {
                const int ks = (k < 10 - k) ? k : (10 - k);  // symmetric tap
                aV[i] = fma2(gw2[ks], v,  aV[i]);
                aS[i] = fma2(gw2[ks], sq, aS[i]);
                aC[i] += gw[ks] * cr;
            }
        }
    }
    const int r0 = gi * 8;
#pragma unroll
    for (int i = 0; i < 8; i++) {
        vhV[r0 + i][cc] = aV[i];
        vhS[r0 + i][cc] = aS[i];
        vhC[r0 + i][cc] = aC[i];
    }
}

__launch_bounds__(NTH, 3)
__global__ void ssim_fused(const float* __restrict__ img1,
                           const float* __restrict__ img2,
                           float* __restrict__ out) {
    __shared__ __align__(16) u64   vhV[TY][PSTRIDE];   // (hx, hy)    18944 B
    __shared__ __align__(16) u64   vhS[TY][PSTRIDE];   // (hxx, hyy)  18944 B
    __shared__ __align__(16) float vhC[TY][CSTRIDE];   // hxy          9728 B
    __shared__ float wpart[NTH / 32];

    // only 6 distinct taps kept live (symmetry)
    const float gw[6] = {GW0, GW1, GW2, GW3, GW4, GW5};
    u64 gw2[6];
#pragma unroll
    for (int k = 0; k < 6; k++) gw2[k] = pack2(gw[k], gw[k]);

    const int tid   = threadIdx.x;
    const int plane = blockIdx.z;
    const int row0  = blockIdx.y * TY;
    const int col0  = blockIdx.x * TX;
    const float* p1 = img1 + (size_t)plane * (W * H);
    const float* p2 = img2 + (size_t)plane * (W * H);

    // ---------------- Phase A: vertical pass --------------------------------
    if (tid < 4 * NCOL) {
        const bool interior = (row0 >= HALO) && (row0 + TY + HALO <= H) &&
                              (col0 >= HALO) && (col0 + TX + HALO <= W);
        if (interior)
            phaseA<false>(p1, p2, row0, col0, tid, vhV, vhS, vhC, gw, gw2);
        else
            phaseA<true >(p1, p2, row0, col0, tid, vhV, vhS, vhC, gw, gw2);
    }
    __syncthreads();

    // ---------------- Phase B: horizontal pass + SSIM -----------------------
    // Column-major mapping (r = tid&31) keeps LDS conflict-light.
    // Sequential quantity passes (V -> S -> C) keep the live register window
    // small so each smem element is loaded into registers exactly once.
    float local = 0.f;
    if (tid < 256) {
        const int r  = tid & 31;
        const int c0 = (tid >> 5) * 8;   // output col group (even -> 16B aligned)

        const float C1 = 1e-4f;
        const float C2 = 9e-4f;

        // -- pass 1: V = (mu1, mu2) packed --
        u64 mV[8];
        {
            u64 fV[18];
            const ulonglong2* rp = reinterpret_cast<const ulonglong2*>(&vhV[r][c0]);
#pragma unroll
            for (int v = 0; v < 9; v++) { ulonglong2 t = rp[v]; fV[2*v] = t.x; fV[2*v+1] = t.y; }
#pragma unroll
            for (int i = 0; i < 8; i++) {
                u64 acc = 0ull;
#pragma unroll
                for (int k = 0; k < 11; k++) {
                    const int ks = (k < 10 - k) ? k : (10 - k);
                    acc = fma2(gw2[ks], fV[i + k], acc);
                }
                mV[i] = acc;
            }
        }

        // -- pass 2: S = (vxx, vyy); fold with mV into 3 scalars per output --
        float mu12[8], musq[8], ssum[8];
        {
            u64 fS[18];
            const ulonglong2* rp = reinterpret_cast<const ulonglong2*>(&vhS[r][c0]);
#pragma unroll
            for (int v = 0; v < 9; v++) { ulonglong2 t = rp[v]; fS[2*v] = t.x; fS[2*v+1] = t.y; }
#pragma unroll
            for (int i = 0; i < 8; i++) {
                u64 acc = 0ull;
#pragma unroll
                for (int k = 0; k < 11; k++) {
                    const int ks = (k < 10 - k) ? k : (10 - k);
                    acc = fma2(gw2[ks], fS[i + k], acc);
                }
                float mu1, mu2, vxx, vyy;
                unpack2(mV[i], mu1, mu2);
                unpack2(acc,   vxx, vyy);
                const float ms = mu1 * mu1 + mu2 * mu2;
                mu12[i] = mu1 * mu2;
                musq[i] = ms;
                ssum[i] = (vxx + vyy) - ms;     // s1 + s2
            }
        }

        // -- pass 3: C = vxy; finish SSIM --
        {
            float fC[20];
            const float4* rp = reinterpret_cast<const float4*>(&vhC[r][c0]);
#pragma unroll
            for (int v = 0; v < 5; v++) {
                float4 t = rp[v];
                fC[4*v+0] = t.x; fC[4*v+1] = t.y; fC[4*v+2] = t.z; fC[4*v+3] = t.w;
            }
#pragma unroll
            for (int i = 0; i < 8; i++) {
                float mC = 0.f;
#pragma unroll
                for (int k = 0; k < 11; k++) {
                    const int ks = (k < 10 - k) ? k : (10 - k);
                    mC += gw[ks] * fC[i + k];
                }
                const float s12 = mC - mu12[i];
                const float num = (2.f * mu12[i] + C1) * (2.f * s12 + C2);
                const float den = (musq[i] + C1) * (ssum[i] + C2 + 1e-6f);
                local += __fdividef(num, den);
            }
        }
    }

    // ---------------- Reduction ----------------------------------------------
#pragma unroll
    for (int off = 16; off > 0; off >>= 1)
        local += __shfl_down_sync(0xffffffffu, local, off);
    if ((tid & 31) == 0) wpart[tid >> 5] = local;
    __syncthreads();
    if (tid == 0) {
        float bs = 0.f;
#pragma unroll
        for (int wv = 0; wv < NTH / 32; wv++) bs += wpart[wv];
        atomicAdd(&g_accum, (double)bs);
        __threadfence();
        const unsigned total = gridDim.x * gridDim.y * gridDim.z;
        if (atomicAdd(&g_count, 1u) == total - 1) {
            const double acc = atomicAdd(&g_accum, 0.0);
            out[0] = (float)(acc / ((double)PLANES * (double)W * (double)H));
            g_accum = 0.0;   // reset so every graph replay is identical
            g_count = 0u;
        }
    }
}

extern "C" void kernel_launch(void* const* d_in, const int* in_sizes, int n_in,
                              void* d_out, int out_size) {
    const float* img1 = (const float*)d_in[0];
    const float* img2 = (const float*)d_in[1];
    float* out = (float*)d_out;

    dim3 grid(W / TX, H / TY, PLANES);
    ssim_fused<<<grid, NTH>>>(img1, img2, out);
}

// round 8
// speedup vs baseline: 1.3916x; 1.1448x over previous
#include <cuda_runtime.h>

#define W 512
#define H 512
#define PLANES 48
#define TX 64          // output tile width
#define TY 32          // output tile height
#define HALO 5
#define NCOL 74        // TX + 2*HALO columns of intermediates
#define PSTRIDE 74     // u64 stride (148 words ≡ 20 mod 32 -> conflict-free 16B loads)
#define NTH 320

typedef unsigned long long u64;

__device__ double g_accum;
__device__ unsigned int g_count;

// Gaussian taps exp(-d^2/4.5), normalized in double at compile time.
#define E0d 1.0
#define E1d 0.8007374029168081
#define E2d 0.4111122905071874
#define E3d 0.1353352832366127
#define E4d 0.0285655007845531
#define E5d 0.0038659201394728
#define ESd (E0d + 2.0*(E1d+E2d+E3d+E4d+E5d))
#define GW0 ((float)(E5d/ESd))
#define GW1 ((float)(E4d/ESd))
#define GW2 ((float)(E3d/ESd))
#define GW3 ((float)(E2d/ESd))
#define GW4 ((float)(E1d/ESd))
#define GW5 ((float)(E0d/ESd))

__device__ __forceinline__ u64 pack2(float a, float b) {
    u64 r; asm("mov.b64 %0, {%1, %2};" : "=l"(r) : "f"(a), "f"(b)); return r;
}
__device__ __forceinline__ void unpack2(u64 v, float& a, float& b) {
    asm("mov.b64 {%0, %1}, %2;" : "=f"(a), "=f"(b) : "l"(v));
}
__device__ __forceinline__ u64 fma2(u64 a, u64 b, u64 c) {
    u64 d; asm("fma.rn.f32x2 %0, %1, %2, %3;" : "=l"(d) : "l"(a), "l"(b), "l"(c)); return d;
}

// Vertical pass: one column strip per thread, 8 output rows from 18 input
// rows, all in registers. Two packed chains: (x,y) and (x^2+y^2, x*y).
template<bool GUARD>
__device__ __forceinline__ void phaseA(const float* __restrict__ p1,
                                       const float* __restrict__ p2,
                                       int row0, int col0, int tid,
                                       u64 (*vhV)[PSTRIDE], u64 (*vhZ)[PSTRIDE],
                                       const u64* gw2) {
    const int gi = tid / NCOL;          // row group 0..3
    const int cc = tid - gi * NCOL;     // column 0..73
    const int gc = col0 + cc - HALO;
    const int rbase = row0 + gi * 8 - HALO;
    const bool colOk = !GUARD || ((unsigned)gc < (unsigned)W);

    u64 aV[8], aZ[8];
#pragma unroll
    for (int i = 0; i < 8; i++) { aV[i] = 0ull; aZ[i] = 0ull; }

#pragma unroll
    for (int j = 0; j < 18; j++) {
        const int gr = rbase + j;
        float x = 0.f, y = 0.f;
        if (!GUARD || (colOk && (unsigned)gr < (unsigned)H)) {
            const int off = gr * W + gc;
            x = p1[off];
            y = p2[off];
        }
        const u64 v  = pack2(x, y);
        const float xy = x * y;
        const float z  = fmaf(y, y, x * x);   // x^2 + y^2
        const u64 zc = pack2(z, xy);
#pragma unroll
        for (int i = 0; i < 8; i++) {
            const int k = j - i;        // compile-time tap index
            if (k >= 0 && k < 11) {
                const int ks = (k < 10 - k) ? k : (10 - k);  // symmetric tap
                aV[i] = fma2(gw2[ks], v,  aV[i]);
                aZ[i] = fma2(gw2[ks], zc, aZ[i]);
            }
        }
    }
    const int r0 = gi * 8;
#pragma unroll
    for (int i = 0; i < 8; i++) {
        vhV[r0 + i][cc] = aV[i];
        vhZ[r0 + i][cc] = aZ[i];
    }
}

__launch_bounds__(NTH, 3)
__global__ void ssim_fused(const float* __restrict__ img1,
                           const float* __restrict__ img2,
                           float* __restrict__ out) {
    __shared__ __align__(16) u64 vhV[TY][PSTRIDE];   // (hx, hy)          18944 B
    __shared__ __align__(16) u64 vhZ[TY][PSTRIDE];   // (hxx+hyy, hxy)    18944 B
    __shared__ float wpart[NTH / 32];

    // only 6 distinct taps kept live (symmetry)
    u64 gw2[6];
    {
        const float gwv[6] = {GW0, GW1, GW2, GW3, GW4, GW5};
#pragma unroll
        for (int k = 0; k < 6; k++) gw2[k] = pack2(gwv[k], gwv[k]);
    }

    const int tid   = threadIdx.x;
    const int plane = blockIdx.z;
    const int row0  = blockIdx.y * TY;
    const int col0  = blockIdx.x * TX;
    const float* p1 = img1 + (size_t)plane * (W * H);
    const float* p2 = img2 + (size_t)plane * (W * H);

    // ---------------- Phase A: vertical pass --------------------------------
    if (tid < 4 * NCOL) {
        const bool interior = (row0 >= HALO) && (row0 + TY + HALO <= H) &&
                              (col0 >= HALO) && (col0 + TX + HALO <= W);
        if (interior)
            phaseA<false>(p1, p2, row0, col0, tid, vhV, vhZ, gw2);
        else
            phaseA<true >(p1, p2, row0, col0, tid, vhV, vhZ, gw2);
    }
    __syncthreads();

    // ---------------- Phase B: horizontal pass + SSIM -----------------------
    // Column-major mapping (r = tid&31) keeps LDS conflict-free.
    float local = 0.f;
    if (tid < 256) {
        const int r  = tid & 31;
        const int c0 = (tid >> 5) * 8;   // output col group (even -> 16B aligned)

        const float C1 = 1e-4f;
        const float C2 = 9e-4f;
        const float C2E = C2 + 1e-6f;

        // -- pass 1: V = (mu1, mu2) packed --
        u64 mV[8];
        {
            u64 fV[18];
            const ulonglong2* rp = reinterpret_cast<const ulonglong2*>(&vhV[r][c0]);
#pragma unroll
            for (int v = 0; v < 9; v++) { ulonglong2 t = rp[v]; fV[2*v] = t.x; fV[2*v+1] = t.y; }
#pragma unroll
            for (int i = 0; i < 8; i++) {
                u64 acc = 0ull;
#pragma unroll
                for (int k = 0; k < 11; k++) {
                    const int ks = (k < 10 - k) ? k : (10 - k);
                    acc = fma2(gw2[ks], fV[i + k], acc);
                }
                mV[i] = acc;
            }
        }

        // -- pass 2: Z = (conv(x2+y2), conv(xy)); finish SSIM -----------------
        {
            u64 fZ[18];
            const ulonglong2* rp = reinterpret_cast<const ulonglong2*>(&vhZ[r][c0]);
#pragma unroll
            for (int v = 0; v < 9; v++) { ulonglong2 t = rp[v]; fZ[2*v] = t.x; fZ[2*v+1] = t.y; }
#pragma unroll
            for (int i = 0; i < 8; i++) {
                u64 acc = 0ull;
#pragma unroll
                for (int k = 0; k < 11; k++) {
                    const int ks = (k < 10 - k) ? k : (10 - k);
                    acc = fma2(gw2[ks], fZ[i + k], acc);
                }
                float mu1, mu2, z, mxy;
                unpack2(mV[i], mu1, mu2);
                unpack2(acc,   z,   mxy);
                const float musq = fmaf(mu1, mu1, mu2 * mu2);
                const float mu12 = mu1 * mu2;
                const float ssum = z   - musq;   // sigma1_sq + sigma2_sq
                const float s12  = mxy - mu12;
                const float num = fmaf(2.f, mu12, C1) * fmaf(2.f, s12, C2);
                const float den = (musq + C1) * (ssum + C2E);
                local += __fdividef(num, den);
            }
        }
    }

    // ---------------- Reduction ----------------------------------------------
#pragma unroll
    for (int off = 16; off > 0; off >>= 1)
        local += __shfl_down_sync(0xffffffffu, local, off);
    if ((tid & 31) == 0) wpart[tid >> 5] = local;
    __syncthreads();
    if (tid == 0) {
        float bs = 0.f;
#pragma unroll
        for (int wv = 0; wv < NTH / 32; wv++) bs += wpart[wv];
        atomicAdd(&g_accum, (double)bs);
        __threadfence();
        const unsigned total = gridDim.x * gridDim.y * gridDim.z;
        if (atomicAdd(&g_count, 1u) == total - 1) {
            const double acc = atomicAdd(&g_accum, 0.0);
            out[0] = (float)(acc / ((double)PLANES * (double)W * (double)H));
            g_accum = 0.0;   // reset so every graph replay is identical
            g_count = 0u;
        }
    }
}

extern "C" void kernel_launch(void* const* d_in, const int* in_sizes, int n_in,
                              void* d_out, int out_size) {
    const float* img1 = (const float*)d_in[0];
    const float* img2 = (const float*)d_in[1];
    float* out = (float*)d_out;

    dim3 grid(W / TX, H / TY, PLANES);
    ssim_fused<<<grid, NTH>>>(img1, img2, out);
}